// round 6
// baseline (speedup 1.0000x reference)
#include <cuda_runtime.h>
#include <cuda_bf16.h>
#include <math.h>
#include <stdint.h>

#define NB 8
#define BATCH 256
#define NV 14062
#define NV3 (NV*3)          // 42186
#define KD 120              // 63 pose-corr + 55 bsw + 2 zero pad (T excluded)
#define NTILE 96            // comps per block = 32 vertices exactly
#define VTILE 32
#define MTILE 64            // batches per M-tile iteration
#define NBLKS ((NV3 + NTILE - 1) / NTILE)   // 440
#define ST_PITCH 100        // staging row pitch (floats)

#define SB_WORDS (15*12*66)         // 11880 (full-K B frags)
#define ST_WORDS (MTILE*ST_PITCH)   // 6400
#define SMEM_BYTES ((SB_WORDS + ST_WORDS)*4)   // 73120

// scratch (allocation-free requirement -> device globals)
__device__ __align__(16) uint32_t g_coefA[BATCH * KD];   // tf32 bits, A-fragment order
__device__ __align__(16) float    g_R[BATCH * NB * 9];   // per-bone rotations
__device__ __align__(16) float    g_bone[BATCH * NB * 12];

struct Aff { float r[9]; float t[3]; };

__device__ __forceinline__ Aff amul(const Aff& A, const Aff& B) {
    Aff C;
#pragma unroll
    for (int i = 0; i < 3; i++) {
#pragma unroll
        for (int j = 0; j < 3; j++)
            C.r[i*3+j] = A.r[i*3+0]*B.r[0*3+j] + A.r[i*3+1]*B.r[1*3+j] + A.r[i*3+2]*B.r[2*3+j];
        C.t[i] = A.r[i*3+0]*B.t[0] + A.r[i*3+1]*B.t[1] + A.r[i*3+2]*B.t[2] + A.t[i];
    }
    return C;
}

__device__ __forceinline__ Aff ainv_rigid(const Aff& A) {
    Aff C;
#pragma unroll
    for (int i = 0; i < 3; i++)
#pragma unroll
        for (int j = 0; j < 3; j++)
            C.r[i*3+j] = A.r[j*3+i];
#pragma unroll
    for (int i = 0; i < 3; i++)
        C.t[i] = -(C.r[i*3+0]*A.t[0] + C.r[i*3+1]*A.t[1] + C.r[i*3+2]*A.t[2]);
    return C;
}

__device__ __forceinline__ void rodrigues(const float* rv, float* R) {
    float x = rv[0], y = rv[1], z = rv[2];
    float d = x*x + y*y + z*z + 1e-12f;
    float ang = sqrtf(d);
    float inv = 1.0f / ang;
    float kx = x*inv, ky = y*inv, kz = z*inv;
    float s = sinf(ang), c = cosf(ang);
    float kk = kx*kx + ky*ky + kz*kz;
    float oc = 1.0f - c;
    R[0] = 1.0f + oc*(kx*kx - kk);
    R[1] = -s*kz + oc*(kx*ky);
    R[2] =  s*ky + oc*(kx*kz);
    R[3] =  s*kz + oc*(ky*kx);
    R[4] = 1.0f + oc*(ky*ky - kk);
    R[5] = -s*kx + oc*(ky*kz);
    R[6] = -s*ky + oc*(kz*kx);
    R[7] =  s*kx + oc*(kz*ky);
    R[8] = 1.0f + oc*(kz*kz - kk);
}

__device__ __forceinline__ uint32_t to_tf32(float f) {
    uint32_t u;
    asm("cvt.rna.tf32.f32 %0, %1;" : "=r"(u) : "f"(f));
    return u;
}

// write coef value k for batch b into m16n8k8 A-fragment-ordered g_coefA
__device__ __forceinline__ void store_coef(int b, int k, float v) {
    int b64  = b >> 6;
    int mblk = (b >> 4) & 3;
    int r    = b & 15;
    int g    = r & 7;
    int hi   = r >> 3;
    int k8 = k >> 3, t = k & 7, tig = t & 3, j2 = t >> 2;
    int lane = g*4 + tig;
    int reg  = j2*2 + hi;
    g_coefA[(((b64*15 + k8)*4 + mblk)*32 + lane)*4 + reg] = to_tf32(v);
}

// prep1: one block per batch; threads 0-7 do one Rodrigues each (+ theta_zero
// coefs for bones 1-7), threads 8-62 copy bsw coefs. k=118,119 stay zero.
__global__ void prep1_kernel(const float* __restrict__ theta,
                             const float* __restrict__ bsw) {
    const int b = blockIdx.x;
    const int t = threadIdx.x;
    if (t < 8) {
        float R[9];
        rodrigues(theta + (b*NB + t)*3, R);
#pragma unroll
        for (int i = 0; i < 9; i++) g_R[(b*NB + t)*9 + i] = R[i];
        if (t >= 1) {
#pragma unroll
            for (int i = 0; i < 3; i++)
#pragma unroll
                for (int j = 0; j < 3; j++)
                    store_coef(b, (t-1)*9 + i*3 + j, R[i*3+j] - (i == j ? 1.0f : 0.0f));
        }
    } else if (t < 63) {
        int j = t - 8;
        store_coef(b, 63 + j, bsw[b*55 + j]);
    }
}

// prep2: FK chain + inverse binds per batch.
__global__ void prep2_kernel(const float* __restrict__ L2P) {
    const int b = blockIdx.x * 32 + threadIdx.x;
    if (b >= BATCH) return;

    Aff M, rest;
#pragma unroll
    for (int n = 0; n < NB; n++) {
        Aff l2p;
#pragma unroll
        for (int i = 0; i < 3; i++) {
#pragma unroll
            for (int j = 0; j < 3; j++) l2p.r[i*3+j] = L2P[n*16 + i*4 + j];
            l2p.t[i] = L2P[n*16 + i*4 + 3];
        }
        Aff loc;
#pragma unroll
        for (int i = 0; i < 9; i++) loc.r[i] = g_R[(b*NB + n)*9 + i];
        loc.t[0] = loc.t[1] = loc.t[2] = 0.0f;

        Aff An = amul(l2p, loc);
        M    = (n == 0) ? An  : amul(M, An);
        rest = (n == 0) ? l2p : amul(rest, l2p);

        Aff w2l = ainv_rigid(rest);
        Aff G = amul(M, w2l);

        float* gp = g_bone + b*(NB*12) + n*12;
#pragma unroll
        for (int i = 0; i < 3; i++) {
            gp[i*4+0] = G.r[i*3+0];
            gp[i*4+1] = G.r[i*3+1];
            gp[i*4+2] = G.r[i*3+2];
            gp[i*4+3] = G.t[i];
        }
    }
}

// Fused tf32 GEMM + epilogue, B-stationary.
// Grid = 440 N-blocks. Per block: fill full-K B tile once (47.5KB smem,
// fragment order), then loop 4 M-tiles of 64 batches: MMA mainloop with A
// fragments read straight from g_coefA (global, fragment-ordered, L1-hot),
// stage C in smem, fused larynx+T+LBS epilogue, direct out write.
__global__ __launch_bounds__(256, 3)
void fused_kernel(const float* __restrict__ P,
                  const float* __restrict__ E,
                  const float* __restrict__ T,
                  const float* __restrict__ W,
                  const float* __restrict__ ts,
                  const float* __restrict__ uvgrid,
                  const float* __restrict__ L,
                  const float* __restrict__ tau,
                  const float* __restrict__ alpha,
                  float* __restrict__ out) {
    extern __shared__ __align__(16) char smem_raw[];
    uint32_t* sB = (uint32_t*)smem_raw;
    float*    st = (float*)(sB + SB_WORDS);

    const int tid   = threadIdx.x;
    const int lane  = tid & 31;
    const int wid   = tid >> 5;
    const int warpM = wid >> 2;      // 0..1
    const int warpN = wid & 3;       // 0..3
    const int cbase = blockIdx.x * NTILE;
    const int vbase = blockIdx.x * VTILE;

    // ---- fill full-K B tile [120 x 96] in fragment order (once) ----
    for (int idx = tid; idx < KD*NTILE; idx += 256) {
        int kl = idx / NTILE;            // 0..119
        int cl = idx - kl*NTILE;         // 0..95
        int c  = cbase + cl;
        float v = 0.0f;
        if (c < NV3) {
            if (kl < 63)       v = P[(size_t)(kl+9)*NV3 + c];
            else if (kl < 118) v = E[(size_t)(kl-63)*NV3 + c];
        }
        int k8 = kl >> 3, t = kl & 7, tig = t & 3, j = t >> 2;
        int nblk = cl >> 3, gg = cl & 7;
        sB[k8*(12*66) + nblk*66 + (gg*4 + tig)*2 + j] = to_tf32(v);
    }

    // ---- hoist per-vertex epilogue constants (same vertex across M-tiles) ----
    const int vl = tid & 31;
    const int r0 = tid >> 5;
    const int v  = vbase + vl;
    float Tx=0, Ty=0, Tz=0, tsx=0, tsy=0, tsz=0, uy=0, wx=0;
    int x0=0, x1=0;
    float w8[NB];
#pragma unroll
    for (int n = 0; n < NB; n++) w8[n] = 0.0f;
    if (v < NV) {
        Tx = T[v*3+0]; Ty = T[v*3+1]; Tz = T[v*3+2];
        tsx = ts[v*3+0]; tsy = ts[v*3+1]; tsz = ts[v*3+2];
#pragma unroll
        for (int n = 0; n < NB; n++) w8[n] = W[n*NV + v];
        float ux = uvgrid[v*2+0];
        uy = uvgrid[v*2+1];
        float x = fminf(fmaxf(ux * 255.0f, 0.0f), 255.0f);
        x0 = (int)floorf(x);
        x1 = min(x0 + 1, 255);
        wx = x - (float)x0;
    }

    __syncthreads();

    // ---- M-tile loop ----
    for (int mt = 0; mt < 4; mt++) {
        const uint32_t* Ag = g_coefA + mt*(MTILE*KD);   // fragment-ordered slice
        const int Mbase = mt * MTILE;

        float acc[2][3][4];
#pragma unroll
        for (int mi = 0; mi < 2; mi++)
#pragma unroll
            for (int ni = 0; ni < 3; ni++)
#pragma unroll
                for (int q = 0; q < 4; q++) acc[mi][ni][q] = 0.0f;

#pragma unroll
        for (int k8 = 0; k8 < 15; k8++) {
            uint32_t a[2][4];
#pragma unroll
            for (int mi = 0; mi < 2; mi++) {
                uint4 av = *(const uint4*)&Ag[((k8*4 + warpM*2 + mi)*32 + lane)*4];
                a[mi][0] = av.x; a[mi][1] = av.y; a[mi][2] = av.z; a[mi][3] = av.w;
            }
            uint32_t bf[3][2];
#pragma unroll
            for (int ni = 0; ni < 3; ni++) {
                uint2 bv = *(const uint2*)&sB[k8*(12*66) + (warpN*3 + ni)*66 + lane*2];
                bf[ni][0] = bv.x; bf[ni][1] = bv.y;
            }
#pragma unroll
            for (int mi = 0; mi < 2; mi++)
#pragma unroll
                for (int ni = 0; ni < 3; ni++) {
                    asm volatile(
                        "mma.sync.aligned.m16n8k8.row.col.f32.tf32.tf32.f32 "
                        "{%0,%1,%2,%3}, {%4,%5,%6,%7}, {%8,%9}, {%0,%1,%2,%3};"
                        : "+f"(acc[mi][ni][0]), "+f"(acc[mi][ni][1]),
                          "+f"(acc[mi][ni][2]), "+f"(acc[mi][ni][3])
                        : "r"(a[mi][0]), "r"(a[mi][1]), "r"(a[mi][2]), "r"(a[mi][3]),
                          "r"(bf[ni][0]), "r"(bf[ni][1]));
                }
        }

        __syncthreads();   // previous epilogue done reading staging
        {
            const int gg  = lane >> 2;
            const int tt4 = lane & 3;
#pragma unroll
            for (int mi = 0; mi < 2; mi++) {
#pragma unroll
                for (int ni = 0; ni < 3; ni++) {
                    int row = warpM*32 + mi*16 + gg;
                    int col = warpN*24 + ni*8 + tt4*2;
                    *(float2*)&st[row*ST_PITCH + col] =
                        make_float2(acc[mi][ni][0], acc[mi][ni][1]);
                    *(float2*)&st[(row+8)*ST_PITCH + col] =
                        make_float2(acc[mi][ni][2], acc[mi][ni][3]);
                }
            }
        }
        __syncthreads();

        // epilogue: thread owns vertex v, 8 batch rows (warp-uniform batch)
        if (v < NV) {
#pragma unroll
            for (int i = 0; i < 8; i++) {
                const int row = r0 + i*8;
                const int b = Mbase + row;
                const float tb = tau[b];
                const float al = alpha[b];

                float y = fminf(fmaxf((uy + tb) * 255.0f, 0.0f), 255.0f);
                int y0 = (int)floorf(y);
                int y1 = min(y0 + 1, 255);
                float wy = y - (float)y0;
                float v00 = L[y0*256 + x0], v01 = L[y0*256 + x1];
                float v10 = L[y1*256 + x0], v11 = L[y1*256 + x1];
                float dist = (v00*(1.0f-wx) + v01*wx)*(1.0f-wy)
                           + (v10*(1.0f-wx) + v11*wx)*wy;
                float s = al * dist;

                float px = st[row*ST_PITCH + vl*3+0] + Tx + s*tsx;
                float py = st[row*ST_PITCH + vl*3+1] + Ty + s*tsy;
                float pz = st[row*ST_PITCH + vl*3+2] + Tz + s*tsz;

                const float4* Gb = (const float4*)(g_bone + b*(NB*12));
                float ox = 0.0f, oy = 0.0f, oz = 0.0f;
#pragma unroll
                for (int n = 0; n < NB; n++) {
                    float4 q0 = Gb[n*3 + 0];   // broadcast across warp
                    float4 q1 = Gb[n*3 + 1];
                    float4 q2 = Gb[n*3 + 2];
                    float wn = w8[n];
                    ox = fmaf(wn, fmaf(q0.x, px, fmaf(q0.y, py, fmaf(q0.z, pz, q0.w))), ox);
                    oy = fmaf(wn, fmaf(q1.x, px, fmaf(q1.y, py, fmaf(q1.z, pz, q1.w))), oy);
                    oz = fmaf(wn, fmaf(q2.x, px, fmaf(q2.y, py, fmaf(q2.z, pz, q2.w))), oz);
                }
                size_t base = (size_t)b * NV3 + (size_t)v * 3;
                out[base + 0] = ox;
                out[base + 1] = oy;
                out[base + 2] = oz;
            }
        }
    }
}

extern "C" void kernel_launch(void* const* d_in, const int* in_sizes, int n_in,
                              void* d_out, int out_size) {
    const float* theta  = (const float*)d_in[0];
    const float* tau    = (const float*)d_in[1];
    const float* alpha  = (const float*)d_in[2];
    const float* bsw    = (const float*)d_in[3];
    const float* W      = (const float*)d_in[4];
    const float* T      = (const float*)d_in[5];
    const float* P      = (const float*)d_in[6];
    const float* L      = (const float*)d_in[7];
    const float* ts     = (const float*)d_in[8];
    const float* L2P    = (const float*)d_in[9];
    const float* E      = (const float*)d_in[10];
    const float* uvgrid = (const float*)d_in[11];
    float* out = (float*)d_out;

    cudaFuncSetAttribute(fused_kernel,
                         cudaFuncAttributeMaxDynamicSharedMemorySize, SMEM_BYTES);

    prep1_kernel<<<BATCH, 64>>>(theta, bsw);
    prep2_kernel<<<8, 32>>>(L2P);

    fused_kernel<<<NBLKS, 256, SMEM_BYTES>>>(P, E, T, W, ts, uvgrid, L, tau,
                                             alpha, out);
}

// round 7
// speedup vs baseline: 1.4579x; 1.4579x over previous
#include <cuda_runtime.h>
#include <cuda_bf16.h>
#include <math.h>
#include <stdint.h>

#define NB 8
#define BATCH 256
#define NV 14062
#define NV3 (NV*3)          // 42186
#define KD 120              // 63 pose-corr + 55 bsw + 2 zero pad (T excluded)
#define NTILE 96            // comps per block = 32 vertices exactly
#define VTILE 32
#define MTILE 64            // batches per M-tile iteration
#define NBLKS ((NV3 + NTILE - 1) / NTILE)   // 440
#define ST_PITCH 100        // staging row pitch (floats)

#define SB_WORDS (15*12*66)         // 11880 (full-K B frags)
#define ST_WORDS (MTILE*ST_PITCH)   // 6400
#define SMEM_BYTES ((SB_WORDS + ST_WORDS)*4)   // 73120

// scratch (allocation-free requirement -> device globals)
__device__ __align__(16) uint32_t g_coefA[BATCH * KD];   // tf32 bits, A-fragment order
__device__ __align__(16) float    g_bone[BATCH * NB * 12];

struct Aff { float r[9]; float t[3]; };

__device__ __forceinline__ Aff amul(const Aff& A, const Aff& B) {
    Aff C;
#pragma unroll
    for (int i = 0; i < 3; i++) {
#pragma unroll
        for (int j = 0; j < 3; j++)
            C.r[i*3+j] = A.r[i*3+0]*B.r[0*3+j] + A.r[i*3+1]*B.r[1*3+j] + A.r[i*3+2]*B.r[2*3+j];
        C.t[i] = A.r[i*3+0]*B.t[0] + A.r[i*3+1]*B.t[1] + A.r[i*3+2]*B.t[2] + A.t[i];
    }
    return C;
}

__device__ __forceinline__ Aff ainv_rigid(const Aff& A) {
    Aff C;
#pragma unroll
    for (int i = 0; i < 3; i++)
#pragma unroll
        for (int j = 0; j < 3; j++)
            C.r[i*3+j] = A.r[j*3+i];
#pragma unroll
    for (int i = 0; i < 3; i++)
        C.t[i] = -(C.r[i*3+0]*A.t[0] + C.r[i*3+1]*A.t[1] + C.r[i*3+2]*A.t[2]);
    return C;
}

__device__ __forceinline__ void rodrigues(const float* rv, float* R) {
    float x = rv[0], y = rv[1], z = rv[2];
    float d = x*x + y*y + z*z + 1e-12f;
    float ang = sqrtf(d);
    float inv = 1.0f / ang;
    float kx = x*inv, ky = y*inv, kz = z*inv;
    float s = sinf(ang), c = cosf(ang);
    float kk = kx*kx + ky*ky + kz*kz;
    float oc = 1.0f - c;
    R[0] = 1.0f + oc*(kx*kx - kk);
    R[1] = -s*kz + oc*(kx*ky);
    R[2] =  s*ky + oc*(kx*kz);
    R[3] =  s*kz + oc*(ky*kx);
    R[4] = 1.0f + oc*(ky*ky - kk);
    R[5] = -s*kx + oc*(ky*kz);
    R[6] = -s*ky + oc*(kz*kx);
    R[7] =  s*kx + oc*(kz*ky);
    R[8] = 1.0f + oc*(kz*kz - kk);
}

__device__ __forceinline__ uint32_t to_tf32(float f) {
    uint32_t u;
    asm("cvt.rna.tf32.f32 %0, %1;" : "=r"(u) : "f"(f));
    return u;
}

// write coef value k for batch b into m16n8k8 A-fragment-ordered g_coefA
__device__ __forceinline__ void store_coef(int b, int k, float v) {
    int b64  = b >> 6;
    int mblk = (b >> 4) & 3;
    int r    = b & 15;
    int g    = r & 7;
    int hi   = r >> 3;
    int k8 = k >> 3, t = k & 7, tig = t & 3, j2 = t >> 2;
    int lane = g*4 + tig;
    int reg  = j2*2 + hi;
    g_coefA[(((b64*15 + k8)*4 + mblk)*32 + lane)*4 + reg] = to_tf32(v);
}

// Merged prep: one block per batch.
// Threads 0-7: Rodrigues (R into smem; theta_zero coefs for bones 1-7).
// Threads 8-62: bsw coefs. After sync, thread 0: FK chain + inverse binds.
__global__ void prep_kernel(const float* __restrict__ theta,
                            const float* __restrict__ bsw,
                            const float* __restrict__ L2P) {
    __shared__ float sR[NB * 9];
    const int b = blockIdx.x;
    const int t = threadIdx.x;
    if (t < 8) {
        float R[9];
        rodrigues(theta + (b*NB + t)*3, R);
#pragma unroll
        for (int i = 0; i < 9; i++) sR[t*9 + i] = R[i];
        if (t >= 1) {
#pragma unroll
            for (int i = 0; i < 3; i++)
#pragma unroll
                for (int j = 0; j < 3; j++)
                    store_coef(b, (t-1)*9 + i*3 + j, R[i*3+j] - (i == j ? 1.0f : 0.0f));
        }
    } else if (t < 63) {
        int j = t - 8;
        store_coef(b, 63 + j, bsw[b*55 + j]);
    }
    __syncthreads();

    if (t == 0) {
        Aff M, rest;
#pragma unroll
        for (int n = 0; n < NB; n++) {
            Aff l2p;
#pragma unroll
            for (int i = 0; i < 3; i++) {
#pragma unroll
                for (int j = 0; j < 3; j++) l2p.r[i*3+j] = L2P[n*16 + i*4 + j];
                l2p.t[i] = L2P[n*16 + i*4 + 3];
            }
            Aff loc;
#pragma unroll
            for (int i = 0; i < 9; i++) loc.r[i] = sR[n*9 + i];
            loc.t[0] = loc.t[1] = loc.t[2] = 0.0f;

            Aff An = amul(l2p, loc);
            M    = (n == 0) ? An  : amul(M, An);
            rest = (n == 0) ? l2p : amul(rest, l2p);

            Aff w2l = ainv_rigid(rest);
            Aff G = amul(M, w2l);

            float* gp = g_bone + b*(NB*12) + n*12;
#pragma unroll
            for (int i = 0; i < 3; i++) {
                gp[i*4+0] = G.r[i*3+0];
                gp[i*4+1] = G.r[i*3+1];
                gp[i*4+2] = G.r[i*3+2];
                gp[i*4+3] = G.t[i];
            }
        }
    }
}

// Fused tf32 GEMM + epilogue, B-stationary.
// Grid = 440 N-blocks; per block fill full-K B tile once, loop 4 M-tiles.
// Epilogue mapping: thread owns 2 adjacent vertices x 4 batch rows, so the
// 24 g_bone broadcast loads per row are shared by 2 vertices (2x fewer LDG).
__global__ __launch_bounds__(256, 2)
void fused_kernel(const float* __restrict__ P,
                  const float* __restrict__ E,
                  const float* __restrict__ T,
                  const float* __restrict__ W,
                  const float* __restrict__ ts,
                  const float* __restrict__ uvgrid,
                  const float* __restrict__ L,
                  const float* __restrict__ tau,
                  const float* __restrict__ alpha,
                  float* __restrict__ out) {
    extern __shared__ __align__(16) char smem_raw[];
    uint32_t* sB = (uint32_t*)smem_raw;
    float*    st = (float*)(sB + SB_WORDS);

    const int tid   = threadIdx.x;
    const int lane  = tid & 31;
    const int wid   = tid >> 5;
    const int warpM = wid >> 2;      // 0..1
    const int warpN = wid & 3;       // 0..3
    const int cbase = blockIdx.x * NTILE;
    const int vbase = blockIdx.x * VTILE;

    // ---- fill full-K B tile [120 x 96] in fragment order (once) ----
    for (int idx = tid; idx < KD*NTILE; idx += 256) {
        int kl = idx / NTILE;            // 0..119
        int cl = idx - kl*NTILE;         // 0..95
        int c  = cbase + cl;
        float v = 0.0f;
        if (c < NV3) {
            if (kl < 63)       v = P[(size_t)(kl+9)*NV3 + c];
            else if (kl < 118) v = E[(size_t)(kl-63)*NV3 + c];
        }
        int k8 = kl >> 3, t = kl & 7, tig = t & 3, j = t >> 2;
        int nblk = cl >> 3, gg = cl & 7;
        sB[k8*(12*66) + nblk*66 + (gg*4 + tig)*2 + j] = to_tf32(v);
    }

    // ---- epilogue thread mapping: 2 vertices x 4 rows ----
    const int vl2  = tid & 15;          // vertex-pair id
    const int rgrp = tid >> 4;          // row group 0..15 (2 per warp)
    const int vp   = vbase + vl2*2;     // even; NV even => one guard for both
    const bool valid = (vp < NV);

    // hoisted per-vertex state (u = 0,1)
    float hT[2][3], hts[2][3], huy[2], hwx[2], hw8[2][8];
    int hx0[2], hx1[2];
    if (valid) {
#pragma unroll
        for (int u = 0; u < 2; u++) {
            int v = vp + u;
#pragma unroll
            for (int q = 0; q < 3; q++) { hT[u][q] = T[v*3+q]; hts[u][q] = ts[v*3+q]; }
#pragma unroll
            for (int n = 0; n < NB; n++) hw8[u][n] = W[n*NV + v];
            float ux = uvgrid[v*2+0];
            huy[u] = uvgrid[v*2+1];
            float x = fminf(fmaxf(ux * 255.0f, 0.0f), 255.0f);
            hx0[u] = (int)floorf(x);
            hx1[u] = min(hx0[u] + 1, 255);
            hwx[u] = x - (float)hx0[u];
        }
    }

    __syncthreads();

    // ---- M-tile loop ----
    for (int mt = 0; mt < 4; mt++) {
        const uint32_t* Ag = g_coefA + mt*(MTILE*KD);
        const int Mbase = mt * MTILE;

        float acc[2][3][4];
#pragma unroll
        for (int mi = 0; mi < 2; mi++)
#pragma unroll
            for (int ni = 0; ni < 3; ni++)
#pragma unroll
                for (int q = 0; q < 4; q++) acc[mi][ni][q] = 0.0f;

#pragma unroll
        for (int k8 = 0; k8 < 15; k8++) {
            uint32_t a[2][4];
#pragma unroll
            for (int mi = 0; mi < 2; mi++) {
                uint4 av = *(const uint4*)&Ag[((k8*4 + warpM*2 + mi)*32 + lane)*4];
                a[mi][0] = av.x; a[mi][1] = av.y; a[mi][2] = av.z; a[mi][3] = av.w;
            }
            uint32_t bf[3][2];
#pragma unroll
            for (int ni = 0; ni < 3; ni++) {
                uint2 bv = *(const uint2*)&sB[k8*(12*66) + (warpN*3 + ni)*66 + lane*2];
                bf[ni][0] = bv.x; bf[ni][1] = bv.y;
            }
#pragma unroll
            for (int mi = 0; mi < 2; mi++)
#pragma unroll
                for (int ni = 0; ni < 3; ni++) {
                    asm volatile(
                        "mma.sync.aligned.m16n8k8.row.col.f32.tf32.tf32.f32 "
                        "{%0,%1,%2,%3}, {%4,%5,%6,%7}, {%8,%9}, {%0,%1,%2,%3};"
                        : "+f"(acc[mi][ni][0]), "+f"(acc[mi][ni][1]),
                          "+f"(acc[mi][ni][2]), "+f"(acc[mi][ni][3])
                        : "r"(a[mi][0]), "r"(a[mi][1]), "r"(a[mi][2]), "r"(a[mi][3]),
                          "r"(bf[ni][0]), "r"(bf[ni][1]));
                }
        }

        __syncthreads();   // previous epilogue done reading staging
        {
            const int gg  = lane >> 2;
            const int tt4 = lane & 3;
#pragma unroll
            for (int mi = 0; mi < 2; mi++) {
#pragma unroll
                for (int ni = 0; ni < 3; ni++) {
                    int row = warpM*32 + mi*16 + gg;
                    int col = warpN*24 + ni*8 + tt4*2;
                    *(float2*)&st[row*ST_PITCH + col] =
                        make_float2(acc[mi][ni][0], acc[mi][ni][1]);
                    *(float2*)&st[(row+8)*ST_PITCH + col] =
                        make_float2(acc[mi][ni][2], acc[mi][ni][3]);
                }
            }
        }
        __syncthreads();

        // epilogue: 4 rows x 2 vertices per thread; G loads shared per row
        if (valid) {
#pragma unroll
            for (int i = 0; i < 4; i++) {
                const int row = rgrp + i*16;
                const int b = Mbase + row;
                const float tb = tau[b];
                const float al = alpha[b];

                float px[2], py[2], pz[2], ox[2], oy[2], oz[2];
#pragma unroll
                for (int u = 0; u < 2; u++) {
                    float y = fminf(fmaxf((huy[u] + tb) * 255.0f, 0.0f), 255.0f);
                    int y0 = (int)floorf(y);
                    int y1 = min(y0 + 1, 255);
                    float wy = y - (float)y0;
                    float v00 = L[y0*256 + hx0[u]], v01 = L[y0*256 + hx1[u]];
                    float v10 = L[y1*256 + hx0[u]], v11 = L[y1*256 + hx1[u]];
                    float wx = hwx[u];
                    float dist = (v00*(1.0f-wx) + v01*wx)*(1.0f-wy)
                               + (v10*(1.0f-wx) + v11*wx)*wy;
                    float s = al * dist;

                    px[u] = st[row*ST_PITCH + vl2*6 + u*3 + 0] + hT[u][0] + s*hts[u][0];
                    py[u] = st[row*ST_PITCH + vl2*6 + u*3 + 1] + hT[u][1] + s*hts[u][1];
                    pz[u] = st[row*ST_PITCH + vl2*6 + u*3 + 2] + hT[u][2] + s*hts[u][2];
                    ox[u] = 0.0f; oy[u] = 0.0f; oz[u] = 0.0f;
                }

                const float4* Gb = (const float4*)(g_bone + b*(NB*12));
#pragma unroll
                for (int n = 0; n < NB; n++) {
                    float4 q0 = Gb[n*3 + 0];   // shared by both vertices
                    float4 q1 = Gb[n*3 + 1];
                    float4 q2 = Gb[n*3 + 2];
#pragma unroll
                    for (int u = 0; u < 2; u++) {
                        float wn = hw8[u][n];
                        ox[u] = fmaf(wn, fmaf(q0.x, px[u], fmaf(q0.y, py[u], fmaf(q0.z, pz[u], q0.w))), ox[u]);
                        oy[u] = fmaf(wn, fmaf(q1.x, px[u], fmaf(q1.y, py[u], fmaf(q1.z, pz[u], q1.w))), oy[u]);
                        oz[u] = fmaf(wn, fmaf(q2.x, px[u], fmaf(q2.y, py[u], fmaf(q2.z, pz[u], q2.w))), oz[u]);
                    }
                }
                size_t base = (size_t)b * NV3 + (size_t)vp * 3;   // even offset
                *(float2*)&out[base + 0] = make_float2(ox[0], oy[0]);
                *(float2*)&out[base + 2] = make_float2(oz[0], ox[1]);
                *(float2*)&out[base + 4] = make_float2(oy[1], oz[1]);
            }
        }
    }
}

extern "C" void kernel_launch(void* const* d_in, const int* in_sizes, int n_in,
                              void* d_out, int out_size) {
    const float* theta  = (const float*)d_in[0];
    const float* tau    = (const float*)d_in[1];
    const float* alpha  = (const float*)d_in[2];
    const float* bsw    = (const float*)d_in[3];
    const float* W      = (const float*)d_in[4];
    const float* T      = (const float*)d_in[5];
    const float* P      = (const float*)d_in[6];
    const float* L      = (const float*)d_in[7];
    const float* ts     = (const float*)d_in[8];
    const float* L2P    = (const float*)d_in[9];
    const float* E      = (const float*)d_in[10];
    const float* uvgrid = (const float*)d_in[11];
    float* out = (float*)d_out;

    cudaFuncSetAttribute(fused_kernel,
                         cudaFuncAttributeMaxDynamicSharedMemorySize, SMEM_BYTES);

    prep_kernel<<<BATCH, 64>>>(theta, bsw, L2P);

    fused_kernel<<<NBLKS, 256, SMEM_BYTES>>>(P, E, T, W, ts, uvgrid, L, tau,
                                             alpha, out);
}